// round 17
// baseline (speedup 1.0000x reference)
#include <cuda_runtime.h>
#include <cuda_fp16.h>
#include <cstdint>

#define NND 50000
#define NP  50048              // padded to 391*128
#define EE  800000
#define NSPLIT 25088           // 196*128, gather/mlp#2 split point

// ---------------------------------------------------------------------------
// Scratch (device globals; no allocations anywhere)
__device__ int   g_hist[NND];
__device__ int   g_rowptr[NND + 1];
__device__ int   g_cursor[NND];
__device__ uint32_t g_edges[EE];             // src | (r==1)<<31, CSR order by dst
__device__ int   g_invidx[NND];
__device__ int   g_ninv;

// fp16 buffers (hi planes only; value-path is single-term fp16)
__device__ __align__(16) __half g_th[(size_t)NP * 256];   // fp16(MLP_inv(h))
__device__ __align__(16) __half g_xh[(size_t)NP * 256];   // fp16(h) -> res/res2
__device__ __align__(16) __half g_sh[(size_t)NP * 256];   // neigh mean

// Pre-transposed fp16 weights (hi only): Wt[n][k] = W[k][n]
__device__ __align__(16) __half g_iW1[128*256];
__device__ __align__(16) __half g_iW2[128*128];
__device__ __align__(16) __half g_iW3[256*128];
__device__ __align__(16) __half g_aW1[128*256];
__device__ __align__(16) __half g_aW2[128*128];
__device__ __align__(16) __half g_aW3[256*128];
__device__ __align__(16) __half g_pW1[256*256];
__device__ __align__(16) __half g_pW2[256*256];

// ---------------------------------------------------------------------------
__device__ __forceinline__ uint32_t smem_u32_of(const void* p) {
    uint32_t a;
    asm("{ .reg .u64 t; cvta.to.shared.u64 t, %1; cvt.u32.u64 %0, t; }"
        : "=r"(a) : "l"(p));
    return a;
}
#define LDSM4(r, addr)                                                         \
    asm volatile("ldmatrix.sync.aligned.m8n8.x4.shared.b16 {%0,%1,%2,%3}, [%4];" \
        : "=r"((r)[0]), "=r"((r)[1]), "=r"((r)[2]), "=r"((r)[3]) : "r"(addr))
#define CP_ASYNC16(dst, src, sz)                                               \
    asm volatile("cp.async.cg.shared.global [%0], [%1], 16, %2;"               \
        :: "r"(dst), "l"(src), "r"(sz) : "memory")
#define CP_COMMIT() asm volatile("cp.async.commit_group;" ::: "memory")
#define CP_WAIT1()  asm volatile("cp.async.wait_group 1;" ::: "memory")
#define CP_WAIT0()  asm volatile("cp.async.wait_group 0;" ::: "memory")

__device__ __forceinline__ void mma_h(float* d, const uint32_t* a,
                                      const uint32_t* b) {
    asm volatile("mma.sync.aligned.m16n8k16.row.col.f32.f16.f16.f32 "
        "{%0,%1,%2,%3}, {%4,%5,%6,%7}, {%8,%9}, {%0,%1,%2,%3};"
        : "+f"(d[0]), "+f"(d[1]), "+f"(d[2]), "+f"(d[3])
        : "r"(a[0]), "r"(a[1]), "r"(a[2]), "r"(a[3]), "r"(b[0]), "r"(b[1]));
}
__device__ __forceinline__ uint32_t packh2(float a, float b) {
    __half x = __float2half_rn(a), y = __float2half_rn(b);
    return (uint32_t)__half_as_ushort(x) | ((uint32_t)__half_as_ushort(y) << 16);
}
__device__ __forceinline__ void split2(float v0, float v1,
                                       uint32_t& hp, uint32_t& lp) {
    __half h0 = __float2half_rn(v0), h1 = __float2half_rn(v1);
    hp = (uint32_t)__half_as_ushort(h0) | ((uint32_t)__half_as_ushort(h1) << 16);
    lp = packh2(v0 - __half2float(h0), v1 - __half2float(h1));
}

// ---------------------------------------------------------------------------
__global__ void zero_kernel() {
    int i = blockIdx.x * blockDim.x + threadIdx.x;
    if (i < NND) g_hist[i] = 0;
    if (i == 0) g_ninv = 0;
}

__global__ void hist_kernel(const int* __restrict__ dst,
                            const int* __restrict__ inv) {
    int e = blockIdx.x * blockDim.x + threadIdx.x;
    if (e < EE) atomicAdd(&g_hist[__ldg(dst + e)], 1);
    if (e < NND && __ldg(inv + e) == 1) {
        int p = atomicAdd(&g_ninv, 1);
        g_invidx[p] = e;
    }
}

__global__ __launch_bounds__(1024, 1) void scan_kernel() {
    __shared__ int warp_sums[32];
    __shared__ int s_carry;
    int tid = threadIdx.x, lane = tid & 31, w = tid >> 5;
    if (tid == 0) s_carry = 0;
    __syncthreads();
    for (int base = 0; base < NND; base += 1024) {
        int i = base + tid;
        int v = (i < NND) ? g_hist[i] : 0;
        int x = v;
        #pragma unroll
        for (int o = 1; o < 32; o <<= 1) {
            int t = __shfl_up_sync(0xFFFFFFFFu, x, o);
            if (lane >= o) x += t;
        }
        if (lane == 31) warp_sums[w] = x;
        __syncthreads();
        if (w == 0) {
            int y = warp_sums[lane];
            #pragma unroll
            for (int o = 1; o < 32; o <<= 1) {
                int t = __shfl_up_sync(0xFFFFFFFFu, y, o);
                if (lane >= o) y += t;
            }
            warp_sums[lane] = y;
        }
        __syncthreads();
        int excl = s_carry + x - v + (w > 0 ? warp_sums[w - 1] : 0);
        if (i < NND) { g_rowptr[i] = excl; g_cursor[i] = excl; }
        __syncthreads();
        if (tid == 0) s_carry += warp_sums[31];
        __syncthreads();
    }
    if (tid == 0) g_rowptr[NND] = s_carry;
}

__global__ void fill_kernel(const int* __restrict__ src,
                            const int* __restrict__ dst,
                            const int* __restrict__ r) {
    int e = blockIdx.x * blockDim.x + threadIdx.x;
    if (e >= EE) return;
    int d = __ldg(dst + e);
    int pos = atomicAdd(&g_cursor[d], 1);
    g_edges[pos] = (uint32_t)__ldg(src + e)
                 | ((uint32_t)(__ldg(r + e) == 1) << 31);
}

// ---- gather-mean over fp16 messages, node range [nbeg,nend) ----
__global__ __launch_bounds__(256) void gather_kernel(
    const __half* __restrict__ xh, const __half* __restrict__ th,
    __half* __restrict__ oh, int nbeg, int nend)
{
    int wid = nbeg + ((blockIdx.x * 256 + threadIdx.x) >> 5);
    int lane = threadIdx.x & 31;
    if (wid >= nend) return;
    int beg = __ldg(&g_rowptr[wid]), end = __ldg(&g_rowptr[wid + 1]);
    float acc[8];
    #pragma unroll
    for (int j = 0; j < 8; j++) acc[j] = 0.f;
    int e = beg;
    uint32_t pn = (e < end) ? __ldg(&g_edges[e]) : 0u;
    for (; e < end; e++) {
        uint32_t p = pn;
        if (e + 1 < end) pn = __ldg(&g_edges[e + 1]);
        const uint4* row = (const uint4*)(((p >> 31) ? th : xh)
                          + (size_t)(p & 0x7FFFFFFFu) * 256) + lane;
        uint4 w = __ldg(row);
        const uint32_t ww[4] = {w.x, w.y, w.z, w.w};
        #pragma unroll
        for (int j = 0; j < 4; j++) {
            float2 f = __half22float2(*(const __half2*)&ww[j]);
            acc[2*j]   += f.x;
            acc[2*j+1] += f.y;
        }
    }
    float sc = 1.f / fmaxf((float)(end - beg), 1.f);
    uint4 hp;
    uint32_t* hq = (uint32_t*)&hp;
    #pragma unroll
    for (int j = 0; j < 4; j++)
        hq[j] = packh2(acc[2*j] * sc, acc[2*j+1] * sc);
    *(uint4*)(oh + (size_t)wid * 256 + lane * 8) = hp;
}

// All 8 weight transposes (fp16 hi only) in one launch
__global__ void prep_all(const float* W0, const float* W1, const float* W2,
                         const float* W3, const float* W4, const float* W5,
                         const float* W6, const float* W7) {
    int i = blockIdx.x * blockDim.x + threadIdx.x;
    if (i >= 294912) return;
    const int cum[9]  = {0, 32768, 49152, 81920, 114688, 131072, 163840, 229376, 294912};
    const int Ks[8]   = {256, 128, 128, 256, 128, 128, 256, 256};
    const int Ns[8]   = {128, 128, 256, 128, 128, 256, 256, 256};
    int m = 0;
    #pragma unroll
    for (int t = 1; t < 8; t++) if (i >= cum[t]) m = t;
    int j = i - cum[m], K = Ks[m], N = Ns[m];
    int n = j / K, k = j % K;
    const float* W; __half* Th;
    switch (m) {
        case 0: W = W0; Th = g_iW1; break;
        case 1: W = W1; Th = g_iW2; break;
        case 2: W = W2; Th = g_iW3; break;
        case 3: W = W3; Th = g_aW1; break;
        case 4: W = W4; Th = g_aW2; break;
        case 5: W = W5; Th = g_aW3; break;
        case 6: W = W6; Th = g_pW1; break;
        default: W = W7; Th = g_pW2; break;
    }
    Th[j] = __float2half_rn(W[(size_t)k * N + n]);
}

// fp32 [NND x 256] -> fp16 hi only
__global__ void conv_hi(const float* __restrict__ x, __half* __restrict__ oh) {
    int u = blockIdx.x * blockDim.x + threadIdx.x;
    if (u >= NND * 32) return;
    int row = u >> 5, seg = u & 31;
    const float4* s = (const float4*)(x + (size_t)row * 256 + seg * 8);
    float4 a = s[0], b = s[1];
    uint4 hp;
    uint32_t* hq = (uint32_t*)&hp;
    hq[0] = packh2(a.x, a.y);
    hq[1] = packh2(a.z, a.w);
    hq[2] = packh2(b.x, b.y);
    hq[3] = packh2(b.z, b.w);
    *(uint4*)(oh + (size_t)row * 256 + seg * 8) = hp;
}

// ---------------------------------------------------------------------------
// Fused 3-layer MLP (fp16, single-term gmem input, 2-term smem inter):
// 256 ->(leaky) 128 ->(leaky) 128 -> 256
// SMEM: buf0@0 (48KB) buf1@49152, inter@98304 (64KB), idx@163840
__global__ __launch_bounds__(256, 1) void mlp3_fused(
    const __half* __restrict__ Ah,
    const __half* __restrict__ W1, const float* __restrict__ b1,
    const __half* __restrict__ W2, const float* __restrict__ b2,
    const __half* __restrict__ W3, const float* __restrict__ b3,
    __half* __restrict__ outh,
    const int* __restrict__ gin, const int* __restrict__ gout,
    const int* __restrict__ nrowp, int rbase)
{
    extern __shared__ char sm[];
    const uint32_t smb = smem_u32_of(sm);
    const int tid = threadIdx.x, lane = tid & 31, warp = tid >> 5;
    const int warp_m = warp & 3, warp_n = warp >> 2;
    const int r0 = rbase + blockIdx.x * 128;
    const uint32_t S = smb;
    const uint32_t IH0 = smb + 98304u, IH1 = smb + 114688u;
    const uint32_t IL0 = smb + 131072u, IL1 = smb + 147456u;

    const int nrow = nrowp ? __ldg(nrowp) : NND;
    if (r0 >= nrow) return;

    int* sidx_in  = (int*)(sm + 163840);
    int* sidx_out = (int*)(sm + 164352);
    for (int i = tid; i < 128; i += 256) {
        int gr = r0 + i;
        bool ok = gr < nrow;
        sidx_in[i]  = ok ? (gin  ? __ldg(gin  + gr) : gr) : -1;
        sidx_out[i] = ok ? (gout ? __ldg(gout + gr) : gr) : -1;
    }
    __syncthreads();

    float c[2][8][4];
    auto zero_c = [&]() {
        #pragma unroll
        for (int i = 0; i < 2; i++)
            #pragma unroll
            for (int j = 0; j < 8; j++)
                #pragma unroll
                for (int k = 0; k < 4; k++) c[i][j][k] = 0.f;
    };

    auto stageA = [&](const __half* src, uint32_t dstb, int k0) {
        #pragma unroll
        for (int it = 0; it < 4; it++) {
            int u = tid + it * 256, row = u >> 3, seg = u & 7;
            int grow = sidx_in[row];
            uint32_t sz = (grow >= 0) ? 16u : 0u;
            const void* sp = src + (size_t)(grow >= 0 ? grow : 0) * 256 + k0 + seg * 8;
            CP_ASYNC16(dstb + (uint32_t)row * 128 + ((uint32_t)(seg ^ (row & 7)) << 4),
                       sp, sz);
        }
    };
    auto stageB = [&](const __half* src, uint32_t dstb, int rows, int K, int k0) {
        for (int u = tid; u < rows * 8; u += 256) {
            int row = u >> 3, seg = u & 7;
            CP_ASYNC16(dstb + (uint32_t)row * 128 + ((uint32_t)(seg ^ (row & 7)) << 4),
                       src + (size_t)row * K + k0 + seg * 8, 16u);
        }
    };

    auto mma_chunk = [&](uint32_t AHb, uint32_t ALb, uint32_t Bb, bool useAL) {
        #pragma unroll
        for (int ks = 0; ks < 4; ks++) {
            uint32_t ah[2][4], al[2][4];
            #pragma unroll
            for (int mt = 0; mt < 2; mt++) {
                int lr = warp_m * 32 + mt * 16 + (lane & 15);
                int seg = 2 * ks + (lane >> 4);
                uint32_t off = (uint32_t)lr * 128 + ((uint32_t)(seg ^ (lr & 7)) << 4);
                LDSM4(ah[mt], AHb + off);
                if (useAL) LDSM4(al[mt], ALb + off);
            }
            #pragma unroll
            for (int nq = 0; nq < 4; nq++) {
                int lrb = warp_n * 64 + nq * 16 + (lane & 7) + ((lane >> 4) << 3);
                int segb = 2 * ks + ((lane >> 3) & 1);
                uint32_t offb = (uint32_t)lrb * 128 + ((uint32_t)(segb ^ (lrb & 7)) << 4);
                uint32_t bh[4];
                LDSM4(bh, Bb + offb);
                #pragma unroll
                for (int mt = 0; mt < 2; mt++) {
                    #pragma unroll
                    for (int sub = 0; sub < 2; sub++) {
                        float* d = c[mt][nq * 2 + sub];
                        mma_h(d, ah[mt], bh + sub * 2);
                        if (useAL) mma_h(d, al[mt], bh + sub * 2);
                    }
                }
            }
        }
    };

    auto epi_smem = [&](const float* __restrict__ bias) {
        #pragma unroll
        for (int mt = 0; mt < 2; mt++) {
            #pragma unroll
            for (int q = 0; q < 8; q++) {
                int col = warp_n * 64 + q * 8 + (lane & 3) * 2;
                float2 bv = *(const float2*)(bias + col);
                uint32_t chb = ((col >> 6) ? IH1 : IH0);
                int cc = col & 63;
                #pragma unroll
                for (int half = 0; half < 2; half++) {
                    int lr = warp_m * 32 + mt * 16 + (lane >> 2) + half * 8;
                    float v0 = c[mt][q][half * 2 + 0] + bv.x;
                    float v1 = c[mt][q][half * 2 + 1] + bv.y;
                    v0 = (v0 >= 0.f) ? v0 : 0.01f * v0;
                    v1 = (v1 >= 0.f) ? v1 : 0.01f * v1;
                    uint32_t hp, lp;
                    split2(v0, v1, hp, lp);
                    uint32_t addr = chb + (uint32_t)lr * 128
                                  + ((uint32_t)((cc >> 3) ^ (lr & 7)) << 4)
                                  + (uint32_t)(cc & 7) * 2;
                    asm volatile("st.shared.b32 [%0], %1;" :: "r"(addr), "r"(hp) : "memory");
                    asm volatile("st.shared.b32 [%0], %1;" :: "r"(addr + 32768u), "r"(lp) : "memory");
                }
            }
        }
    };

    // ---- Layer 1: K=256, 4 chunks, double-buffered, single-term A ----
    zero_c();
    {
        auto stage1 = [&](int ch, int buf) {
            uint32_t base = S + (uint32_t)buf * 49152u;
            stageA(Ah, base, ch * 64);
            stageB(W1, base + 32768u, 128, 256, ch * 64);
            CP_COMMIT();
        };
        stage1(0, 0);
        for (int ch = 0; ch < 4; ch++) {
            int cur = ch & 1;
            if (ch + 1 < 4) {
                stage1(ch + 1, cur ^ 1);
                CP_WAIT1();
            } else {
                stageB(W2, S + 0u,     128, 128, 0);
                stageB(W2, S + 16384u, 128, 128, 64);
                CP_COMMIT();
                CP_WAIT1();
            }
            __syncthreads();
            uint32_t base = S + (uint32_t)cur * 49152u;
            mma_chunk(base, 0u, base + 32768u, false);
            __syncthreads();
        }
    }
    stageB(W3, S + 32768u, 256, 128, 0);
    stageB(W3, S + 65536u, 256, 128, 64);
    CP_COMMIT();
    epi_smem(b1);
    CP_WAIT1();
    __syncthreads();

    // ---- Layer 2: K=128, A = inter (2-term), B = W2 ----
    zero_c();
    mma_chunk(IH0, IL0, S + 0u, true);
    mma_chunk(IH1, IL1, S + 16384u, true);
    __syncthreads();
    epi_smem(b2);
    CP_WAIT0();
    __syncthreads();

    // ---- Layer 3: K=128, N=256 (two column halves), linear ----
    #pragma unroll
    for (int hf = 0; hf < 2; hf++) {
        zero_c();
        mma_chunk(IH0, IL0, S + 32768u + (uint32_t)hf * 16384u, true);
        mma_chunk(IH1, IL1, S + 65536u + (uint32_t)hf * 16384u, true);
        #pragma unroll
        for (int mt = 0; mt < 2; mt++) {
            #pragma unroll
            for (int q = 0; q < 8; q++) {
                int col = hf * 128 + warp_n * 64 + q * 8 + (lane & 3) * 2;
                float2 bv = *(const float2*)(b3 + col);
                #pragma unroll
                for (int half = 0; half < 2; half++) {
                    int lr = warp_m * 32 + mt * 16 + (lane >> 2) + half * 8;
                    int orow = sidx_out[lr];
                    if (orow >= 0) {
                        float v0 = c[mt][q][half * 2 + 0] + bv.x;
                        float v1 = c[mt][q][half * 2 + 1] + bv.y;
                        *(uint32_t*)(outh + (size_t)orow * 256 + col) = packh2(v0, v1);
                    }
                }
            }
        }
    }
}

// ---------------------------------------------------------------------------
// Fused projection head: 256 ->(relu) 256 -> 256 (fp32 out).
// A (4 K-chunks, 64KB) resident; W tiles (16KB) double-buffered; hidden in
// 4 fp16-hi SMEM planes (64KB, same precision as previous gmem round-trip).
// SMEM: A@0 (65536), BB@65536 (2x16384), IN@98304 (4x16384) = 163840.
__global__ __launch_bounds__(256, 1) void proj_fused(
    const __half* __restrict__ Ah,
    const __half* __restrict__ W1, const float* __restrict__ b1,
    const __half* __restrict__ W2, const float* __restrict__ b2,
    float* __restrict__ out)
{
    extern __shared__ char sm[];
    const uint32_t smb = smem_u32_of(sm);
    const int tid = threadIdx.x, lane = tid & 31, warp = tid >> 5;
    const int warp_m = warp & 3, warp_n = warp >> 2;
    const int r0 = blockIdx.x * 128;
    const uint32_t BB = smb + 65536u, IN = smb + 98304u;

    float c[2][8][4];
    auto zero_c = [&]() {
        #pragma unroll
        for (int i = 0; i < 2; i++)
            #pragma unroll
            for (int j = 0; j < 8; j++)
                #pragma unroll
                for (int k = 0; k < 4; k++) c[i][j][k] = 0.f;
    };

    // W tile (hf, ch): rows hf*128..+128 of Wt[256][256], cols ch*64..+64
    auto stageW = [&](const __half* src, int hf, int ch, int buf) {
        #pragma unroll
        for (int it = 0; it < 4; it++) {
            int u = tid + it * 256, row = u >> 3, seg = u & 7;
            CP_ASYNC16(BB + (uint32_t)buf * 16384u + (uint32_t)row * 128
                       + ((uint32_t)(seg ^ (row & 7)) << 4),
                       src + (size_t)(hf * 128 + row) * 256 + ch * 64 + seg * 8, 16u);
        }
    };

    auto mma64 = [&](uint32_t Abase, uint32_t Bbase) {
        #pragma unroll
        for (int ks = 0; ks < 4; ks++) {
            uint32_t ah[2][4];
            #pragma unroll
            for (int mt = 0; mt < 2; mt++) {
                int lr = warp_m * 32 + mt * 16 + (lane & 15);
                int seg = 2 * ks + (lane >> 4);
                LDSM4(ah[mt], Abase + (uint32_t)lr * 128
                              + ((uint32_t)(seg ^ (lr & 7)) << 4));
            }
            #pragma unroll
            for (int nq = 0; nq < 4; nq++) {
                int lrb = warp_n * 64 + nq * 16 + (lane & 7) + ((lane >> 4) << 3);
                int segb = 2 * ks + ((lane >> 3) & 1);
                uint32_t bh[4];
                LDSM4(bh, Bbase + (uint32_t)lrb * 128
                          + ((uint32_t)(segb ^ (lrb & 7)) << 4));
                #pragma unroll
                for (int mt = 0; mt < 2; mt++) {
                    #pragma unroll
                    for (int sub = 0; sub < 2; sub++)
                        mma_h(c[mt][nq * 2 + sub], ah[mt], bh + sub * 2);
                }
            }
        }
    };

    // initial stage: A all 4 chunks + W1 tile (0,0)
    #pragma unroll
    for (int ch = 0; ch < 4; ch++) {
        #pragma unroll
        for (int it = 0; it < 4; it++) {
            int u = tid + it * 256, row = u >> 3, seg = u & 7;
            int grow = r0 + row;
            uint32_t sz = (grow < NND) ? 16u : 0u;
            CP_ASYNC16(smb + (uint32_t)ch * 16384u + (uint32_t)row * 128
                       + ((uint32_t)(seg ^ (row & 7)) << 4),
                       Ah + (size_t)(grow < NND ? grow : 0) * 256 + ch * 64 + seg * 8,
                       sz);
        }
    }
    stageW(W1, 0, 0, 0);
    CP_COMMIT();

    // 16-tile pipeline: g 0..7 = L1 (A from gmem-staged), g 8..15 = L2 (A = IN)
    for (int g = 0; g < 16; g++) {
        int buf = g & 1;
        if (g < 15) {
            int ng = g + 1;
            const __half* W = (ng < 8) ? W1 : W2;
            int t = ng & 7;
            stageW(W, t >> 2, t & 3, ng & 1);
            CP_COMMIT();
            CP_WAIT1();
        } else {
            CP_WAIT0();
        }
        __syncthreads();
        int t = g & 7, hf = t >> 2, ch = t & 3;
        if (ch == 0) zero_c();
        uint32_t Abase = (g < 8) ? (smb + (uint32_t)ch * 16384u)
                                 : (IN + (uint32_t)ch * 16384u);
        mma64(Abase, BB + (uint32_t)buf * 16384u);
        if (ch == 3) {
            if (g < 8) {
                // L1 epilogue: relu -> IN planes (fp16 hi), cols hf*128..
                #pragma unroll
                for (int mt = 0; mt < 2; mt++) {
                    #pragma unroll
                    for (int q = 0; q < 8; q++) {
                        int col = hf * 128 + warp_n * 64 + q * 8 + (lane & 3) * 2;
                        float2 bv = *(const float2*)(b1 + col);
                        uint32_t chb = IN + (uint32_t)(col >> 6) * 16384u;
                        int cc = col & 63;
                        #pragma unroll
                        for (int half = 0; half < 2; half++) {
                            int lr = warp_m * 32 + mt * 16 + (lane >> 2) + half * 8;
                            float v0 = fmaxf(c[mt][q][half * 2 + 0] + bv.x, 0.f);
                            float v1 = fmaxf(c[mt][q][half * 2 + 1] + bv.y, 0.f);
                            uint32_t addr = chb + (uint32_t)lr * 128
                                          + ((uint32_t)((cc >> 3) ^ (lr & 7)) << 4)
                                          + (uint32_t)(cc & 7) * 2;
                            uint32_t hp = packh2(v0, v1);
                            asm volatile("st.shared.b32 [%0], %1;"
                                         :: "r"(addr), "r"(hp) : "memory");
                        }
                    }
                }
            } else {
                // L2 epilogue: bias -> fp32 out
                #pragma unroll
                for (int mt = 0; mt < 2; mt++) {
                    #pragma unroll
                    for (int q = 0; q < 8; q++) {
                        int col = hf * 128 + warp_n * 64 + q * 8 + (lane & 3) * 2;
                        float2 bv = *(const float2*)(b2 + col);
                        #pragma unroll
                        for (int half = 0; half < 2; half++) {
                            int lr = warp_m * 32 + mt * 16 + (lane >> 2) + half * 8;
                            int orow = r0 + lr;
                            if (orow < NND) {
                                float v0 = c[mt][q][half * 2 + 0] + bv.x;
                                float v1 = c[mt][q][half * 2 + 1] + bv.y;
                                *(float2*)(out + (size_t)orow * 256 + col)
                                    = make_float2(v0, v1);
                            }
                        }
                    }
                }
            }
        }
        __syncthreads();
    }
}

// ---------------------------------------------------------------------------
extern "C" void kernel_launch(void* const* d_in, const int* in_sizes, int n_in,
                              void* d_out, int out_size)
{
    const float* h   = (const float*)d_in[0];
    const int*   src = (const int*)  d_in[1];
    const int*   dst = (const int*)  d_in[2];
    const int*   r   = (const int*)  d_in[3];
    const int*   inv = (const int*)  d_in[4];
    const float* iW1 = (const float*)d_in[5];
    const float* ib1 = (const float*)d_in[6];
    const float* iW2 = (const float*)d_in[7];
    const float* ib2 = (const float*)d_in[8];
    const float* iW3 = (const float*)d_in[9];
    const float* ib3 = (const float*)d_in[10];
    const float* aW1 = (const float*)d_in[11];
    const float* ab1 = (const float*)d_in[12];
    const float* aW2 = (const float*)d_in[13];
    const float* ab2 = (const float*)d_in[14];
    const float* aW3 = (const float*)d_in[15];
    const float* ab3 = (const float*)d_in[16];
    const float* pW1 = (const float*)d_in[17];
    const float* pb1 = (const float*)d_in[18];
    const float* pW2 = (const float*)d_in[19];
    const float* pb2 = (const float*)d_in[20];
    float* out = (float*)d_out;

    int *invidx, *ninv;
    cudaGetSymbolAddress((void**)&invidx, g_invidx);
    cudaGetSymbolAddress((void**)&ninv, g_ninv);

    __half *th,*xh,*sh;
    cudaGetSymbolAddress((void**)&th, g_th);
    cudaGetSymbolAddress((void**)&xh, g_xh);
    cudaGetSymbolAddress((void**)&sh, g_sh);

    __half *wi1,*wi2,*wi3,*wa1,*wa2,*wa3,*wp1,*wp2;
    cudaGetSymbolAddress((void**)&wi1, g_iW1);
    cudaGetSymbolAddress((void**)&wi2, g_iW2);
    cudaGetSymbolAddress((void**)&wi3, g_iW3);
    cudaGetSymbolAddress((void**)&wa1, g_aW1);
    cudaGetSymbolAddress((void**)&wa2, g_aW2);
    cudaGetSymbolAddress((void**)&wa3, g_aW3);
    cudaGetSymbolAddress((void**)&wp1, g_pW1);
    cudaGetSymbolAddress((void**)&wp2, g_pW2);

    const int SMEM_F = 164864;   // fused MLP
    const int SMEM_P = 163840;   // fused proj
    cudaFuncSetAttribute(mlp3_fused, cudaFuncAttributeMaxDynamicSharedMemorySize, SMEM_F);
    cudaFuncSetAttribute(proj_fused, cudaFuncAttributeMaxDynamicSharedMemorySize, SMEM_P);

    // Secondary stream + events (created once; capture-safe fork/join pattern)
    static cudaStream_t s2 = nullptr;
    static cudaEvent_t evFork = nullptr, evJoin = nullptr, evG0 = nullptr, evG2 = nullptr;
    if (!s2) {
        cudaStreamCreateWithFlags(&s2, cudaStreamNonBlocking);
        cudaEventCreateWithFlags(&evFork, cudaEventDisableTiming);
        cudaEventCreateWithFlags(&evJoin, cudaEventDisableTiming);
        cudaEventCreateWithFlags(&evG0,   cudaEventDisableTiming);
        cudaEventCreateWithFlags(&evG2,   cudaEventDisableTiming);
    }

    const int NB = (NND + 127) / 128;   // 391
    const int NB1 = NSPLIT / 128;       // 196
    const int NB2 = NB - NB1;           // 195

    // fork: CSR build on s2, overlapped with prep/conv/tinv-MLP on stream 0
    cudaEventRecord(evFork, 0);
    cudaStreamWaitEvent(s2, evFork, 0);
    zero_kernel<<<196, 256, 0, s2>>>();
    hist_kernel<<<(EE + 255) / 256, 256, 0, s2>>>(dst, inv);
    scan_kernel<<<1, 1024, 0, s2>>>();
    fill_kernel<<<(EE + 255) / 256, 256, 0, s2>>>(src, dst, r);
    cudaEventRecord(evJoin, s2);

    prep_all<<<1152, 256>>>(iW1, iW2, iW3, aW1, aW2, aW3, pW1, pW2);
    conv_hi<<<6250, 256>>>(h, xh);
    // th = fp16(MLP_inv(h))
    mlp3_fused<<<NB, 256, SMEM_F>>>(xh, wi1, ib1, wi2, ib2, wi3, ib3,
                                    th, 0, 0, 0, 0);
    cudaStreamWaitEvent(0, evJoin, 0);     // CSR ready on main

    // split gather: half2 on s2 (after th+CSR), half1 on main
    cudaEventRecord(evG0, 0);
    cudaStreamWaitEvent(s2, evG0, 0);
    gather_kernel<<<((NND - NSPLIT) * 32 + 255) / 256, 256, 0, s2>>>(
        xh, th, sh, NSPLIT, NND);
    cudaEventRecord(evG2, s2);
    gather_kernel<<<(NSPLIT * 32 + 255) / 256, 256>>>(xh, th, sh, 0, NSPLIT);

    // res = MLP_and(neigh) -> xh, split so half1 overlaps gather-half2
    mlp3_fused<<<NB1, 256, SMEM_F>>>(sh, wa1, ab1, wa2, ab2, wa3, ab3,
                                     xh, 0, 0, 0, 0);
    cudaStreamWaitEvent(0, evG2, 0);
    mlp3_fused<<<NB2, 256, SMEM_F>>>(sh, wa1, ab1, wa2, ab2, wa3, ab3,
                                     xh, 0, 0, 0, NSPLIT);
    // res2[invidx] = MLP_inv(res[invidx])  (compact)
    mlp3_fused<<<NB, 256, SMEM_F>>>(xh, wi1, ib1, wi2, ib2, wi3, ib3,
                                    xh, invidx, invidx, ninv, 0);
    // fused projection head
    proj_fused<<<NB, 256, SMEM_P>>>(xh, wp1, pb1, wp2, pb2, out);
}